// round 16
// baseline (speedup 1.0000x reference)
#include <cuda_runtime.h>
#include <cuda_fp16.h>
#include <math.h>

#define M 4096
#define CN 64
#define BNEPS 1e-5f

typedef unsigned long long u64;

// ---------------- packed f32x2 helpers ----------------------------------------
__device__ __forceinline__ u64 pk(float lo, float hi) {
    u64 r; asm("mov.b64 %0,{%1,%2};" : "=l"(r) : "f"(lo), "f"(hi)); return r;
}
__device__ __forceinline__ void upk(u64 v, float& lo, float& hi) {
    asm("mov.b64 {%0,%1},%2;" : "=f"(lo), "=f"(hi) : "l"(v));
}
__device__ __forceinline__ u64 ffma2(u64 a, u64 b, u64 c) {
    u64 d; asm("fma.rn.f32x2 %0,%1,%2,%3;" : "=l"(d) : "l"(a), "l"(b), "l"(c)); return d;
}

// ---------------- constant-memory weights (warp-UNIFORM access only) ----------
// [0:320) w_rank | [320:352) b_rank | [352:1376) w_h1 | [1376:1408) b_h1
// [1408:1920) w_h2 | [1920:1936) b_h2 | [1936:2064) w_rank pair-packed
__constant__ __align__(16) float c_all[2064];
#define c_wr   (c_all)
#define c_br   (c_all + 320)
#define c_wh1  (c_all + 352)
#define c_bh1  (c_all + 1376)
#define c_wh2  (c_all + 1408)
#define c_bh2  (c_all + 1920)
#define c_wrp  (c_all + 1936)   // [oo][w][2]: (wr[2oo][w], wr[2oo+1][w])

__device__ float g_stage[2064];

// ---------------- scratch (device globals; no allocs allowed) ----------------
__device__ float g_table[5*16*64*16];                 // 320 KB
__device__ int   g_cnt1b[4][80];                      // per-histogram-block partials
__device__ int   g_cnt2b[4][10*256];
__device__ float g_bn1s[CN],  g_bn1q[CN];
__device__ float g_bn2s[CN],  g_bn2q[CN];
__device__ float g_scale0[CN], g_shift0[CN];
__device__ float g_base_r[CN*32];
__device__ float g_rc3[CN*32];
__device__ float g_scale2[CN], g_shift2[CN];
__device__ float g_outconst[16];
__device__ __half2 g_r3h[(size_t)CN*4*16*M];          // 64 MB, [c][h][o2][m]
__device__ __half2 g_r4h[(size_t)CN*32*M];            // 32 MB, [c][h*8+o2][m]

// ---------------- ktable: table (0-79) + histograms (80-83) + pack (84-86) ----
__global__ void __launch_bounds__(1024) ktable(const float* __restrict__ conv_w,
                      const int* __restrict__ x,
                      const float* __restrict__ wr, const float* __restrict__ br,
                      const float* __restrict__ wh1, const float* __restrict__ bh1,
                      const float* __restrict__ wh2, const float* __restrict__ bh2) {
    __shared__ int h1[80];
    __shared__ int h2[2560];
    int bx = blockIdx.x, t = threadIdx.x;
    if (bx < 80) {                                    // table build
        int idx = bx*1024 + t;
        int hw = idx & 15, c = (idx>>4)&63, combo = (idx>>10)&15, i = idx>>14;
        int h = hw>>2, w = hw&3, r = combo>>2, s = combo&3;
        float v = 0.f;
        if (h <= r && w <= s) v = conv_w[c*125 + i*25 + (r-h)*5 + (s-w)];
        g_table[idx] = v;
        return;
    }
    if (bx >= 84) {                                   // weight packing (idempotent)
        int idx = (bx - 84)*1024 + t;
        if (idx >= 2064) return;
        float v;
        if      (idx < 320)  v = wr[idx];
        else if (idx < 352)  v = br[idx - 320];
        else if (idx < 1376) v = wh1[idx - 352];
        else if (idx < 1408) v = bh1[idx - 1376];
        else if (idx < 1920) v = wh2[idx - 1408];
        else if (idx < 1936) v = bh2[idx - 1920];
        else {
            int k = idx - 1936;
            int oo = k >> 3, w = (k >> 1) & 3, half = k & 1;
            v = wr[(2*oo + half)*10 + w];
        }
        g_stage[idx] = v;
        return;
    }
    // histogram blocks (4 x 1024 samples), per-block partials, plain stores
    int hb = bx - 80;
    for (int i = t; i < 80;   i += 1024) h1[i] = 0;
    for (int i = t; i < 2560; i += 1024) h2[i] = 0;
    __syncthreads();
    int m = hb*1024 + t;
    int cb[5];
    const int2* xp = reinterpret_cast<const int2*>(x + m*10);
#pragma unroll
    for (int i = 0; i < 5; i++) {
        int2 cd = xp[i];
        cb[i] = (cd.x & 3)*4 + (cd.y & 3);
    }
#pragma unroll
    for (int i = 0; i < 5; i++) atomicAdd(&h1[i*16 + cb[i]], 1);
    int p = 0;
#pragma unroll
    for (int i = 0; i < 5; i++)
#pragma unroll
        for (int j = i+1; j < 5; j++) {
            atomicAdd(&h2[p*256 + cb[i]*16 + cb[j]], 1);
            p++;
        }
    __syncthreads();
    for (int i = t; i < 80;   i += 1024) g_cnt1b[hb][i] = h1[i];
    for (int i = t; i < 2560; i += 1024) g_cnt2b[hb][i] = h2[i];
}

// Per-block shared slice of the table for channel c (stride 16)
__device__ __forceinline__ void load_stab(float* stab, int c, int t, int nt) {
    for (int idx = t; idx < 1280; idx += nt) {
        int i = idx >> 8, rem = idx & 255;
        stab[idx] = g_table[(i*16 + (rem>>4))*1024 + c*16 + (rem&15)];
    }
}

// ---------------- kbn0k2: BN0 stats from histograms + const path --------------
__global__ void __launch_bounds__(256) kbn0k2(const float* __restrict__ conv_b,
                   const float* __restrict__ bn0_g, const float* __restrict__ bn0_b,
                   const float* __restrict__ w_rank, const float* __restrict__ b_rank,
                   const float* __restrict__ w_h1,  const float* __restrict__ b_h1,
                   const float* __restrict__ b_out) {
    __shared__ float stab17[5*16*17];
    __shared__ float swT[32*33];
    __shared__ float rc2[32];
    __shared__ float red_s, red_q, s_u0;
    __shared__ int spi[10], spj[10];
    int c = blockIdx.x, t = threadIdx.x;
    if (c == 0 && t < 16) g_outconst[t] = (t < 9) ? b_out[t] : 0.f;  // seed for k6 atomics
    for (int idx = t; idx < 1280; idx += 256) {
        int i = idx >> 8, rem = idx & 255;
        stab17[(i*16 + (rem>>4))*17 + (rem&15)] =
            g_table[(i*16 + (rem>>4))*1024 + c*16 + (rem&15)];
    }
    for (int idx = t; idx < 1024; idx += 256) {
        int o = idx >> 5, i = idx & 31;
        swT[i*33 + o] = w_h1[idx];
    }
    if (t == 0) {
        red_s = 0.f; red_q = 0.f;
        int p = 0;
        for (int i = 0; i < 5; i++)
            for (int j = i+1; j < 5; j++) { spi[p] = i; spj[p] = j; p++; }
    }
    __syncthreads();
    float s = 0.f, q = 0.f;
    for (int it = t; it < 80; it += 256) {            // diagonal terms
        int i = it >> 4, ci = it & 15;
        const float* b = &stab17[(i*16 + ci)*17];
        float sd = 0.f, qd = 0.f;
#pragma unroll
        for (int k = 0; k < 16; k++) { float v = b[k]; sd += v; qd += v*v; }
        float cnt = (float)(g_cnt1b[0][it] + g_cnt1b[1][it] +
                            g_cnt1b[2][it] + g_cnt1b[3][it]);
        s += cnt*sd;
        q += cnt*qd;
    }
    for (int it = t; it < 2560; it += 256) {          // cross terms
        int p = it >> 8, ci = (it >> 4) & 15, cj = it & 15;
        int cnt = g_cnt2b[0][it] + g_cnt2b[1][it] + g_cnt2b[2][it] + g_cnt2b[3][it];
        if (cnt) {
            const float* a = &stab17[(spi[p]*16 + ci)*17];
            const float* b = &stab17[(spj[p]*16 + cj)*17];
            float d = 0.f;
#pragma unroll
            for (int k = 0; k < 16; k++) d += a[k]*b[k];
            q += 2.f*(float)cnt*d;
        }
    }
    for (int off = 16; off; off >>= 1) {
        s += __shfl_down_sync(0xffffffffu, s, off);
        q += __shfl_down_sync(0xffffffffu, q, off);
    }
    if ((t & 31) == 0) { atomicAdd(&red_s, s); atomicAdd(&red_q, q); }
    __syncthreads();
    if (t == 0) {
        float n0   = (float)M * 110.0f;
        float mu_a = red_s / n0;
        float var  = red_q / n0 - mu_a*mu_a;
        float cb   = conv_b[c];
        float sc   = bn0_g[c] * rsqrtf(var + BNEPS);
        float sh   = bn0_b[c] - (cb + mu_a)*sc;
        g_scale0[c] = sc;
        g_shift0[c] = sh;
        s_u0 = fmaxf(cb*sc + sh, 0.f);
    }
    __syncthreads();
    if (t < 32) {
        float u0 = s_u0;
        float w4 = 0.f, wall = 0.f;
        for (int w = 0; w < 10; w++) { float v = w_rank[t*10+w]; wall += v; if (w >= 4) w4 += v; }
        float br = b_rank[t];
        g_base_r[c*32 + t] = u0*w4 + br;
        rc2[t] = fmaxf(u0*wall + br, 0.f);
    }
    __syncthreads();
    if (t < 32) {
        float acc = b_h1[t];
#pragma unroll
        for (int i = 0; i < 32; i++) acc += rc2[i] * swT[i*33 + t];
        g_rc3[c*32 + t] = acc;
        float s2 = acc, q2 = acc*acc;
        for (int off = 16; off; off >>= 1) {
            s2 += __shfl_down_sync(0xffffffffu, s2, off);
            q2 += __shfl_down_sync(0xffffffffu, q2, off);
        }
        if (t == 0) {
            g_bn1s[c] = (float)(M*7)*s2;
            g_bn1q[c] = (float)(M*7)*q2;
        }
    }
}

// ---------------- k3: scalar FFMA2, const/smem split weight streams -----------
__global__ void __launch_bounds__(256, 3) k3(const int* __restrict__ x,
                                             const float* __restrict__ conv_b,
                                             const float* __restrict__ w_h1) {
    __shared__ __align__(16) float stab[1280];
    __shared__ __align__(16) float swh1odd[512];      // odd-o rows of w_h1 (2 KB)
    __shared__ u64 sbasep[16];
    __shared__ float red_s, red_q;
    int c = blockIdx.y, t = threadIdx.x;
    load_stab(stab, c, t, 256);
    for (int idx = t; idx < 512; idx += 256)          // row (2*o2+1): offset o2*64+32
        swh1odd[idx] = w_h1[(idx >> 5)*64 + 32 + (idx & 31)];
    if (t < 16) sbasep[t] = pk(g_base_r[c*32 + 2*t], g_base_r[c*32 + 2*t + 1]);
    if (t == 0) {
        red_s = 0.f; red_q = 0.f;
        if (blockIdx.x == 0) { g_bn2s[c] = 0.f; g_bn2q[c] = 0.f; }  // init for k5 atomics
    }
    __syncthreads();

    int hp = t >> 7;                       // h-pair: rows {2hp, 2hp+1}
    int m  = blockIdx.x*128 + (t & 127);
    float sc0 = g_scale0[c];
    float pc0 = conv_b[c]*sc0 + g_shift0[c];

    float a8[8];
#pragma unroll
    for (int k = 0; k < 8; k++) a8[k] = 0.f;
    const int2* xp = reinterpret_cast<const int2*>(x + m*10);
#pragma unroll
    for (int i = 0; i < 5; i++) {
        int2 cd = xp[i];
        const float4* tp = reinterpret_cast<const float4*>(
            stab + i*256 + ((cd.x & 3)*4 + (cd.y & 3))*16 + hp*8);
        float4 t0 = tp[0], t1 = tp[1];
        a8[0]+=t0.x; a8[1]+=t0.y; a8[2]+=t0.z; a8[3]+=t0.w;
        a8[4]+=t1.x; a8[5]+=t1.y; a8[6]+=t1.z; a8[7]+=t1.w;
    }
#pragma unroll
    for (int k = 0; k < 8; k++) a8[k] = fmaxf(a8[k]*sc0 + pc0, 0.f);   // bn0 + relu

    // w_rank stage: pair-packed const weights
    u64 r2p0[16], r2p1[16];
#pragma unroll
    for (int hh = 0; hh < 2; hh++) {
        u64 b0p = pk(a8[hh*4+0], a8[hh*4+0]);
        u64 b1p = pk(a8[hh*4+1], a8[hh*4+1]);
        u64 b2p = pk(a8[hh*4+2], a8[hh*4+2]);
        u64 b3p = pk(a8[hh*4+3], a8[hh*4+3]);
#pragma unroll
        for (int oo = 0; oo < 16; oo++) {
            u64 e = sbasep[oo];
            const ulonglong2* wq = reinterpret_cast<const ulonglong2*>(&c_wrp[oo*8]);
            ulonglong2 wa = wq[0], wb = wq[1];
            e = ffma2(b0p, wa.x, e);
            e = ffma2(b1p, wa.y, e);
            e = ffma2(b2p, wb.x, e);
            e = ffma2(b3p, wb.y, e);
            float e0, e1; upk(e, e0, e1);
            u64 r = pk(fmaxf(e0, 0.f), fmaxf(e1, 0.f));
            if (hh == 0) r2p0[oo] = r; else r2p1[oo] = r;
        }
    }

    // w_h1 stage: even rows from const port, odd rows from smem broadcast
    float s = 0.f, q = 0.f;
    size_t bh0 = (size_t)((c*4 + 2*hp)*16)*M + m;
#pragma unroll 2
    for (int o2 = 0; o2 < 16; o2++) {
        int oe = 2*o2;
        u64 aE0 = pk(c_bh1[oe], 0.f), aE1 = aE0;
        u64 aO0 = pk(c_bh1[oe+1], 0.f), aO1 = aO0;
        const ulonglong2* wpe = reinterpret_cast<const ulonglong2*>(&c_wh1[oe*32]);
        const ulonglong2* wpo = reinterpret_cast<const ulonglong2*>(&swh1odd[o2*32]);
#pragma unroll
        for (int i = 0; i < 8; i++) {
            ulonglong2 we = wpe[i], wo = wpo[i];
            aE0 = ffma2(r2p0[2*i], we.x, aE0); aE0 = ffma2(r2p0[2*i+1], we.y, aE0);
            aE1 = ffma2(r2p1[2*i], we.x, aE1); aE1 = ffma2(r2p1[2*i+1], we.y, aE1);
            aO0 = ffma2(r2p0[2*i], wo.x, aO0); aO0 = ffma2(r2p0[2*i+1], wo.y, aO0);
            aO1 = ffma2(r2p1[2*i], wo.x, aO1); aO1 = ffma2(r2p1[2*i+1], wo.y, aO1);
        }
        float e0l,e0h,e1l,e1h,o0l,o0h,o1l,o1h;
        upk(aE0,e0l,e0h); upk(aE1,e1l,e1h); upk(aO0,o0l,o0h); upk(aO1,o1l,o1h);
        float vE0 = e0l+e0h, vE1 = e1l+e1h, vO0 = o0l+o0h, vO1 = o1l+o1h;
        s += vE0 + vE1 + vO0 + vO1;
        q += vE0*vE0 + vE1*vE1 + vO0*vO0 + vO1*vO1;
        g_r3h[bh0 + (size_t)o2*M]        = __floats2half2_rn(vE0, vO0);   // h0
        g_r3h[bh0 + (size_t)(16+o2)*M]   = __floats2half2_rn(vE1, vO1);   // h0+1
    }
    for (int off = 16; off; off >>= 1) {
        s += __shfl_down_sync(0xffffffffu, s, off);
        q += __shfl_down_sync(0xffffffffu, q, off);
    }
    if ((t & 31) == 0) { atomicAdd(&red_s, s); atomicAdd(&red_q, q); }
    __syncthreads();
    if (t == 0) { atomicAdd(&g_bn1s[c], red_s); atomicAdd(&g_bn1q[c], red_q); }
}

// ---------------- k5: fused bn1+relu -> w_h2, BN2 sums (BN1 finalize inline) --
__global__ void __launch_bounds__(256, 3) k5(const float* __restrict__ bn1_g,
                                             const float* __restrict__ bn1_b,
                                             const float* __restrict__ w_h2) {
    __shared__ __align__(16) float swh2odd[256];      // odd-o rows of w_h2 (1 KB)
    __shared__ float red_s, red_q;
    int c = blockIdx.y, t = threadIdx.x;
    if (t < 256) {
        int idx = t;                                  // row (2*o2+1): offset o2*64+32
        if (idx < 256) swh2odd[idx] = w_h2[(idx >> 5)*64 + 32 + (idx & 31)];
    }
    if (t == 0) { red_s = 0.f; red_q = 0.f; }
    __syncthreads();

    // BN1 finalize (uniform, cheap, redundant per thread)
    float n1   = (float)M * 11.0f * 32.0f;
    float mean = g_bn1s[c] / n1;
    float var  = g_bn1q[c] / n1 - mean*mean;
    float sc1  = bn1_g[c] * rsqrtf(var + BNEPS);
    float sf1  = bn1_b[c] - mean*sc1;

    int hp = t >> 7;
    int m  = blockIdx.x*128 + (t & 127);

    u64 yp0[16], yp1[16];
    size_t rb = (size_t)((c*4 + 2*hp)*16)*M + m;
#pragma unroll
    for (int i2 = 0; i2 < 16; i2++) {
        float2 f = __half22float2(g_r3h[rb + (size_t)i2*M]);
        yp0[i2] = pk(fmaxf(f.x*sc1 + sf1, 0.f), fmaxf(f.y*sc1 + sf1, 0.f));
    }
#pragma unroll
    for (int i2 = 0; i2 < 16; i2++) {
        float2 f = __half22float2(g_r3h[rb + (size_t)(16 + i2)*M]);
        yp1[i2] = pk(fmaxf(f.x*sc1 + sf1, 0.f), fmaxf(f.y*sc1 + sf1, 0.f));
    }

    float s = 0.f, q = 0.f;
    size_t wb = (size_t)(c*32)*M + m;
#pragma unroll 2
    for (int o2 = 0; o2 < 8; o2++) {
        int oe = 2*o2;
        u64 aE0 = pk(c_bh2[oe], 0.f), aE1 = aE0;
        u64 aO0 = pk(c_bh2[oe+1], 0.f), aO1 = aO0;
        const ulonglong2* wpe = reinterpret_cast<const ulonglong2*>(&c_wh2[oe*32]);
        const ulonglong2* wpo = reinterpret_cast<const ulonglong2*>(&swh2odd[o2*32]);
#pragma unroll
        for (int i = 0; i < 8; i++) {
            ulonglong2 we = wpe[i], wo = wpo[i];
            aE0 = ffma2(yp0[2*i], we.x, aE0); aE0 = ffma2(yp0[2*i+1], we.y, aE0);
            aE1 = ffma2(yp1[2*i], we.x, aE1); aE1 = ffma2(yp1[2*i+1], we.y, aE1);
            aO0 = ffma2(yp0[2*i], wo.x, aO0); aO0 = ffma2(yp0[2*i+1], wo.y, aO0);
            aO1 = ffma2(yp1[2*i], wo.x, aO1); aO1 = ffma2(yp1[2*i+1], wo.y, aO1);
        }
        float e0l,e0h,e1l,e1h,o0l,o0h,o1l,o1h;
        upk(aE0,e0l,e0h); upk(aE1,e1l,e1h); upk(aO0,o0l,o0h); upk(aO1,o1l,o1h);
        float vE0 = e0l+e0h, vE1 = e1l+e1h, vO0 = o0l+o0h, vO1 = o1l+o1h;
        s += vE0 + vE1 + vO0 + vO1;
        q += vE0*vE0 + vE1*vE1 + vO0*vO0 + vO1*vO1;
        g_r4h[wb + (size_t)((2*hp)*8   + o2)*M] = __floats2half2_rn(vE0, vO0);
        g_r4h[wb + (size_t)((2*hp+1)*8 + o2)*M] = __floats2half2_rn(vE1, vO1);
    }
    for (int off = 16; off; off >>= 1) {
        s += __shfl_down_sync(0xffffffffu, s, off);
        q += __shfl_down_sync(0xffffffffu, q, off);
    }
    if ((t & 31) == 0) { atomicAdd(&red_s, s); atomicAdd(&red_q, q); }
    __syncthreads();
    if (t == 0) { atomicAdd(&g_bn2s[c], red_s); atomicAdd(&g_bn2q[c], red_q); }
}

// ---------------- k6: const w_h2 path + BN2 finalize + const-row output -------
// 16 blocks x 288 threads. Block b: channels [4b, 4b+4), feature slice 64.
__global__ void __launch_bounds__(288) k6(const float* __restrict__ bn1_g,
                                          const float* __restrict__ bn1_b,
                                          const float* __restrict__ bn2_g,
                                          const float* __restrict__ bn2_b,
                                          const float* __restrict__ w_h2,
                                          const float* __restrict__ b_h2,
                                          const float* __restrict__ w_out) {
    __shared__ float swh2T[32*17];
    __shared__ float rc3bn[4][32];
    __shared__ float rc4s[4][16];
    __shared__ float rc5[64];
    __shared__ float s_sc2[4], s_sh2[4];
    int t = threadIdx.x, b = blockIdx.x;
    int warp = t >> 5, lane = t & 31;
    for (int idx = t; idx < 512; idx += 288) {
        int o = idx >> 5, i = idx & 31;
        swh2T[i*17 + o] = w_h2[idx];
    }
    if (warp < 4) {                                   // BN1 finalize + rc3bn
        int c = b*4 + warp;
        float n1   = (float)M * 11.0f * 32.0f;
        float mean = g_bn1s[c] / n1;
        float var  = g_bn1q[c] / n1 - mean*mean;
        float sc1  = bn1_g[c] * rsqrtf(var + BNEPS);
        float sf1  = bn1_b[c] - mean*sc1;
        rc3bn[warp][lane] = fmaxf(g_rc3[c*32 + lane]*sc1 + sf1, 0.f);
    }
    __syncthreads();
    if (warp < 4) {                                   // const w_h2 matvec + BN2 finalize
        int c = b*4 + warp;
        float acc = 0.f;
        bool act = lane < 16;
        if (act) {
            acc = b_h2[lane];
#pragma unroll
            for (int i = 0; i < 32; i++) acc += rc3bn[warp][i] * swh2T[i*17 + lane];
            rc4s[warp][lane] = acc;
        }
        float s = act ? acc : 0.f, q = act ? acc*acc : 0.f;
        for (int off = 16; off; off >>= 1) {
            s += __shfl_down_sync(0xffffffffu, s, off);
            q += __shfl_down_sync(0xffffffffu, q, off);
        }
        if (lane == 0) {
            float n2   = (float)M * 11.0f * 16.0f;
            float tots = g_bn2s[c] + (float)(M*7)*s;
            float totq = g_bn2q[c] + (float)(M*7)*q;
            float mean = tots / n2;
            float var  = totq / n2 - mean*mean;
            float sc2  = bn2_g[c] * rsqrtf(var + BNEPS);
            float sh2  = bn2_b[c] - mean*sc2;
            g_scale2[c] = sc2;  s_sc2[warp] = sc2;
            g_shift2[c] = sh2;  s_sh2[warp] = sh2;
        }
    }
    __syncthreads();
    if (t < 64) {
        int lc = t >> 4;
        rc5[t] = fmaxf(rc4s[lc][t & 15]*s_sc2[lc] + s_sh2[lc], 0.f);
    }
    __syncthreads();
    int j = warp;
    if (j < 9) {
        float acc = 0.f;
#pragma unroll
        for (int rep = 0; rep < 2; rep++) {
            int p = rep*32 + lane;
            int gp = b*64 + p;
            int c = gp >> 4, o = gp & 15;
            float ws = 0.f;
#pragma unroll
            for (int h = 4; h < 11; h++) ws += w_out[j*11264 + c*176 + h*16 + o];
            acc += rc5[p]*ws;
        }
        for (int off = 16; off; off >>= 1) acc += __shfl_down_sync(0xffffffffu, acc, off);
        if (!lane) atomicAdd(&g_outconst[j], acc);
    }
}

// ---------------- k6b: seed output with constant part -------------------------
__global__ void k6b(float* __restrict__ out) {
    int idx = blockIdx.x*256 + threadIdx.x;
    if (idx < M*9) out[idx] = g_outconst[idx % 9];
}

// ---------------- k7: varying-feature GEMM (bn2+relu fused, fp16 in) ----------
__global__ void __launch_bounds__(256) k7(const float* __restrict__ w_out,
                                          float* __restrict__ out) {
    __shared__ u64 swe[9*32], swo[9*32];
    int t = threadIdx.x;
    int warp = t >> 5, lane = t & 31;
    int mbase = blockIdx.x*1024 + warp*128 + lane*4;
    int c0 = blockIdx.y*2;
    u64 accA[9], accB[9];
#pragma unroll
    for (int j = 0; j < 9; j++) { accA[j] = 0; accB[j] = 0; }
    for (int cc = 0; cc < 2; cc++) {
        int c = c0 + cc;
        __syncthreads();
        for (int idx = t; idx < 576; idx += 256) {
            int j = idx / 64, r = idx % 64, qq2 = r >> 1, eo = r & 1;
            int h = qq2 >> 3, o2 = qq2 & 7;
            float w = w_out[j*11264 + c*176 + h*16 + 2*o2 + eo];
            (eo ? swo : swe)[j*32 + qq2] = pk(w, w);
        }
        __syncthreads();
        float sc = g_scale2[c], sf = g_shift2[c];
        for (int qq2 = 0; qq2 < 32; qq2++) {
            const __half2* row = &g_r4h[(size_t)(c*32 + qq2)*M];
            uint2 ua = *reinterpret_cast<const uint2*>(row + mbase);
            uint2 ub = *reinterpret_cast<const uint2*>(row + mbase + 2);
            float2 f0 = __half22float2(*reinterpret_cast<__half2*>(&ua.x));
            float2 f1 = __half22float2(*reinterpret_cast<__half2*>(&ua.y));
            float2 f2 = __half22float2(*reinterpret_cast<__half2*>(&ub.x));
            float2 f3 = __half22float2(*reinterpret_cast<__half2*>(&ub.y));
            u64 yeA = pk(fmaxf(f0.x*sc+sf, 0.f), fmaxf(f1.x*sc+sf, 0.f));
            u64 yoA = pk(fmaxf(f0.y*sc+sf, 0.f), fmaxf(f1.y*sc+sf, 0.f));
            u64 yeB = pk(fmaxf(f2.x*sc+sf, 0.f), fmaxf(f3.x*sc+sf, 0.f));
            u64 yoB = pk(fmaxf(f2.y*sc+sf, 0.f), fmaxf(f3.y*sc+sf, 0.f));
#pragma unroll
            for (int j = 0; j < 9; j++) {
                u64 we = swe[j*32 + qq2], wo = swo[j*32 + qq2];
                accA[j] = ffma2(yeA, we, accA[j]);
                accA[j] = ffma2(yoA, wo, accA[j]);
                accB[j] = ffma2(yeB, we, accB[j]);
                accB[j] = ffma2(yoB, wo, accB[j]);
            }
        }
    }
#pragma unroll
    for (int j = 0; j < 9; j++) {
        float a0, a1, b0, b1;
        upk(accA[j], a0, a1);
        upk(accB[j], b0, b1);
        atomicAdd(&out[(size_t)mbase*9 + j],     a0);
        atomicAdd(&out[(size_t)(mbase+1)*9 + j], a1);
        atomicAdd(&out[(size_t)(mbase+2)*9 + j], b0);
        atomicAdd(&out[(size_t)(mbase+3)*9 + j], b1);
    }
}

// ---------------- launch ------------------------------------------------------
extern "C" void kernel_launch(void* const* d_in, const int* in_sizes, int n_in,
                              void* d_out, int out_size) {
    const int*   x      = (const int*)  d_in[0];
    const float* conv_w = (const float*)d_in[1];
    const float* conv_b = (const float*)d_in[2];
    const float* bn0_g  = (const float*)d_in[3];
    const float* bn0_b  = (const float*)d_in[4];
    const float* w_rank = (const float*)d_in[5];
    const float* b_rank = (const float*)d_in[6];
    const float* w_h1   = (const float*)d_in[7];
    const float* b_h1   = (const float*)d_in[8];
    const float* bn1_g  = (const float*)d_in[9];
    const float* bn1_b  = (const float*)d_in[10];
    const float* w_h2   = (const float*)d_in[11];
    const float* b_h2   = (const float*)d_in[12];
    const float* bn2_g  = (const float*)d_in[13];
    const float* bn2_b  = (const float*)d_in[14];
    const float* w_out  = (const float*)d_in[15];
    const float* b_out  = (const float*)d_in[16];
    float* out = (float*)d_out;

    ktable<<<87, 1024>>>(conv_w, x, w_rank, b_rank, w_h1, b_h1, w_h2, b_h2);
    void* stage_ptr = nullptr;
    cudaGetSymbolAddress(&stage_ptr, g_stage);
    cudaMemcpyToSymbolAsync(c_all, stage_ptr, 2064*sizeof(float), 0,
                            cudaMemcpyDeviceToDevice, 0);

    kbn0k2<<<64, 256>>>(conv_b, bn0_g, bn0_b, w_rank, b_rank, w_h1, b_h1, b_out);
    k3<<<dim3(32, 64), 256>>>(x, conv_b, w_h1);
    k5<<<dim3(32, 64), 256>>>(bn1_g, bn1_b, w_h2);
    k6<<<16, 288>>>(bn1_g, bn1_b, bn2_g, bn2_b, w_h2, b_h2, w_out);
    k6b<<<144, 256>>>(out);
    k7<<<dim3(4, 32), 256>>>(w_out, out);
}

// round 17
// speedup vs baseline: 1.1256x; 1.1256x over previous
#include <cuda_runtime.h>
#include <cuda_fp16.h>
#include <math.h>

#define M 4096
#define CN 64
#define BNEPS 1e-5f

typedef unsigned long long u64;

// ---------------- packed f32x2 helpers ----------------------------------------
__device__ __forceinline__ u64 pk(float lo, float hi) {
    u64 r; asm("mov.b64 %0,{%1,%2};" : "=l"(r) : "f"(lo), "f"(hi)); return r;
}
__device__ __forceinline__ void upk(u64 v, float& lo, float& hi) {
    asm("mov.b64 {%0,%1},%2;" : "=f"(lo), "=f"(hi) : "l"(v));
}
__device__ __forceinline__ u64 ffma2(u64 a, u64 b, u64 c) {
    u64 d; asm("fma.rn.f32x2 %0,%1,%2,%3;" : "=l"(d) : "l"(a), "l"(b), "l"(c)); return d;
}

// ---------------- constant-memory weights (warp-UNIFORM access only) ----------
// [0:320) w_rank | [320:352) b_rank | [352:1376) w_h1 | [1376:1408) b_h1
// [1408:1920) w_h2 | [1920:1936) b_h2 | [1936:2064) w_rank pair-packed
__constant__ __align__(16) float c_all[2064];
#define c_wr   (c_all)
#define c_br   (c_all + 320)
#define c_wh1  (c_all + 352)
#define c_bh1  (c_all + 1376)
#define c_wh2  (c_all + 1408)
#define c_bh2  (c_all + 1920)
#define c_wrp  (c_all + 1936)   // [oo][w][2]: (wr[2oo][w], wr[2oo+1][w])

__device__ float g_stage[2064];

// ---------------- scratch (device globals; no allocs allowed) ----------------
__device__ float g_table[5*16*64*16];                 // 320 KB
__device__ int   g_cnt1b[4][80];                      // per-histogram-block partials
__device__ int   g_cnt2b[4][10*256];
__device__ float g_bn1s[CN],  g_bn1q[CN];
__device__ float g_bn2s[CN],  g_bn2q[CN];
__device__ float g_scale0[CN], g_shift0[CN];
__device__ float g_base_r[CN*32];
__device__ float g_rc3[CN*32];
__device__ float g_scale2[CN], g_shift2[CN];
__device__ float g_outconst[16];
__device__ __half2 g_r3h[(size_t)CN*4*16*M];          // 64 MB, [c][h][o2][m]
__device__ __half2 g_r4h[(size_t)CN*32*M];            // 32 MB, [c][h*8+o2][m]

// ---------------- ktable: table (0-79) + histograms (80-83) + pack (84-86) ----
__global__ void __launch_bounds__(1024) ktable(const float* __restrict__ conv_w,
                      const int* __restrict__ x,
                      const float* __restrict__ wr, const float* __restrict__ br,
                      const float* __restrict__ wh1, const float* __restrict__ bh1,
                      const float* __restrict__ wh2, const float* __restrict__ bh2) {
    __shared__ int h1[80];
    __shared__ int h2[2560];
    int bx = blockIdx.x, t = threadIdx.x;
    if (bx < 80) {                                    // table build
        int idx = bx*1024 + t;
        int hw = idx & 15, c = (idx>>4)&63, combo = (idx>>10)&15, i = idx>>14;
        int h = hw>>2, w = hw&3, r = combo>>2, s = combo&3;
        float v = 0.f;
        if (h <= r && w <= s) v = conv_w[c*125 + i*25 + (r-h)*5 + (s-w)];
        g_table[idx] = v;
        return;
    }
    if (bx >= 84) {                                   // weight packing (idempotent)
        int idx = (bx - 84)*1024 + t;
        if (idx >= 2064) return;
        float v;
        if      (idx < 320)  v = wr[idx];
        else if (idx < 352)  v = br[idx - 320];
        else if (idx < 1376) v = wh1[idx - 352];
        else if (idx < 1408) v = bh1[idx - 1376];
        else if (idx < 1920) v = wh2[idx - 1408];
        else if (idx < 1936) v = bh2[idx - 1920];
        else {
            int k = idx - 1936;
            int oo = k >> 3, w = (k >> 1) & 3, half = k & 1;
            v = wr[(2*oo + half)*10 + w];
        }
        g_stage[idx] = v;
        return;
    }
    // histogram blocks (4 x 1024 samples), per-block partials, plain stores
    int hb = bx - 80;
    for (int i = t; i < 80;   i += 1024) h1[i] = 0;
    for (int i = t; i < 2560; i += 1024) h2[i] = 0;
    __syncthreads();
    int m = hb*1024 + t;
    int cb[5];
    const int2* xp = reinterpret_cast<const int2*>(x + m*10);
#pragma unroll
    for (int i = 0; i < 5; i++) {
        int2 cd = xp[i];
        cb[i] = (cd.x & 3)*4 + (cd.y & 3);
    }
#pragma unroll
    for (int i = 0; i < 5; i++) atomicAdd(&h1[i*16 + cb[i]], 1);
    int p = 0;
#pragma unroll
    for (int i = 0; i < 5; i++)
#pragma unroll
        for (int j = i+1; j < 5; j++) {
            atomicAdd(&h2[p*256 + cb[i]*16 + cb[j]], 1);
            p++;
        }
    __syncthreads();
    for (int i = t; i < 80;   i += 1024) g_cnt1b[hb][i] = h1[i];
    for (int i = t; i < 2560; i += 1024) g_cnt2b[hb][i] = h2[i];
}

// Per-block shared slice of the table for channel c (stride 16)
__device__ __forceinline__ void load_stab(float* stab, int c, int t, int nt) {
    for (int idx = t; idx < 1280; idx += nt) {
        int i = idx >> 8, rem = idx & 255;
        stab[idx] = g_table[(i*16 + (rem>>4))*1024 + c*16 + (rem&15)];
    }
}

// ---------------- kbn0k2: BN0 stats from histograms + const path --------------
__global__ void __launch_bounds__(256) kbn0k2(const float* __restrict__ conv_b,
                   const float* __restrict__ bn0_g, const float* __restrict__ bn0_b,
                   const float* __restrict__ w_rank, const float* __restrict__ b_rank,
                   const float* __restrict__ w_h1,  const float* __restrict__ b_h1,
                   const float* __restrict__ b_out) {
    __shared__ float stab17[5*16*17];
    __shared__ float swT[32*33];
    __shared__ float rc2[32];
    __shared__ float red_s, red_q, s_u0;
    __shared__ int spi[10], spj[10];
    int c = blockIdx.x, t = threadIdx.x;
    if (c == 0 && t < 16) g_outconst[t] = (t < 9) ? b_out[t] : 0.f;  // seed for k6 atomics
    for (int idx = t; idx < 1280; idx += 256) {
        int i = idx >> 8, rem = idx & 255;
        stab17[(i*16 + (rem>>4))*17 + (rem&15)] =
            g_table[(i*16 + (rem>>4))*1024 + c*16 + (rem&15)];
    }
    for (int idx = t; idx < 1024; idx += 256) {
        int o = idx >> 5, i = idx & 31;
        swT[i*33 + o] = w_h1[idx];
    }
    if (t == 0) {
        red_s = 0.f; red_q = 0.f;
        int p = 0;
        for (int i = 0; i < 5; i++)
            for (int j = i+1; j < 5; j++) { spi[p] = i; spj[p] = j; p++; }
    }
    __syncthreads();
    float s = 0.f, q = 0.f;
    for (int it = t; it < 80; it += 256) {            // diagonal terms
        int i = it >> 4, ci = it & 15;
        const float* b = &stab17[(i*16 + ci)*17];
        float sd = 0.f, qd = 0.f;
#pragma unroll
        for (int k = 0; k < 16; k++) { float v = b[k]; sd += v; qd += v*v; }
        float cnt = (float)(g_cnt1b[0][it] + g_cnt1b[1][it] +
                            g_cnt1b[2][it] + g_cnt1b[3][it]);
        s += cnt*sd;
        q += cnt*qd;
    }
    for (int it = t; it < 2560; it += 256) {          // cross terms
        int p = it >> 8, ci = (it >> 4) & 15, cj = it & 15;
        int cnt = g_cnt2b[0][it] + g_cnt2b[1][it] + g_cnt2b[2][it] + g_cnt2b[3][it];
        if (cnt) {
            const float* a = &stab17[(spi[p]*16 + ci)*17];
            const float* b = &stab17[(spj[p]*16 + cj)*17];
            float d = 0.f;
#pragma unroll
            for (int k = 0; k < 16; k++) d += a[k]*b[k];
            q += 2.f*(float)cnt*d;
        }
    }
    for (int off = 16; off; off >>= 1) {
        s += __shfl_down_sync(0xffffffffu, s, off);
        q += __shfl_down_sync(0xffffffffu, q, off);
    }
    if ((t & 31) == 0) { atomicAdd(&red_s, s); atomicAdd(&red_q, q); }
    __syncthreads();
    if (t == 0) {
        float n0   = (float)M * 110.0f;
        float mu_a = red_s / n0;
        float var  = red_q / n0 - mu_a*mu_a;
        float cb   = conv_b[c];
        float sc   = bn0_g[c] * rsqrtf(var + BNEPS);
        float sh   = bn0_b[c] - (cb + mu_a)*sc;
        g_scale0[c] = sc;
        g_shift0[c] = sh;
        s_u0 = fmaxf(cb*sc + sh, 0.f);
    }
    __syncthreads();
    if (t < 32) {
        float u0 = s_u0;
        float w4 = 0.f, wall = 0.f;
        for (int w = 0; w < 10; w++) { float v = w_rank[t*10+w]; wall += v; if (w >= 4) w4 += v; }
        float br = b_rank[t];
        g_base_r[c*32 + t] = u0*w4 + br;
        rc2[t] = fmaxf(u0*wall + br, 0.f);
    }
    __syncthreads();
    if (t < 32) {
        float acc = b_h1[t];
#pragma unroll
        for (int i = 0; i < 32; i++) acc += rc2[i] * swT[i*33 + t];
        g_rc3[c*32 + t] = acc;
        float s2 = acc, q2 = acc*acc;
        for (int off = 16; off; off >>= 1) {
            s2 += __shfl_down_sync(0xffffffffu, s2, off);
            q2 += __shfl_down_sync(0xffffffffu, q2, off);
        }
        if (t == 0) {
            g_bn1s[c] = (float)(M*7)*s2;
            g_bn1q[c] = (float)(M*7)*q2;
        }
    }
}

// ---------------- k3: scalar FFMA2 (round-15 exact, pure-const weights) -------
__global__ void __launch_bounds__(256, 3) k3(const int* __restrict__ x,
                                             const float* __restrict__ conv_b) {
    __shared__ __align__(16) float stab[1280];
    __shared__ u64 sbasep[16];
    __shared__ float red_s, red_q;
    int c = blockIdx.y, t = threadIdx.x;
    load_stab(stab, c, t, 256);
    if (t < 16) sbasep[t] = pk(g_base_r[c*32 + 2*t], g_base_r[c*32 + 2*t + 1]);
    if (t == 0) {
        red_s = 0.f; red_q = 0.f;
        if (blockIdx.x == 0) { g_bn2s[c] = 0.f; g_bn2q[c] = 0.f; }  // init for k5 atomics
    }
    __syncthreads();

    int hp = t >> 7;                       // h-pair: rows {2hp, 2hp+1}
    int m  = blockIdx.x*128 + (t & 127);
    float sc0 = g_scale0[c];
    float pc0 = conv_b[c]*sc0 + g_shift0[c];

    float a8[8];
#pragma unroll
    for (int k = 0; k < 8; k++) a8[k] = 0.f;
    const int2* xp = reinterpret_cast<const int2*>(x + m*10);
#pragma unroll
    for (int i = 0; i < 5; i++) {
        int2 cd = xp[i];
        const float4* tp = reinterpret_cast<const float4*>(
            stab + i*256 + ((cd.x & 3)*4 + (cd.y & 3))*16 + hp*8);
        float4 t0 = tp[0], t1 = tp[1];
        a8[0]+=t0.x; a8[1]+=t0.y; a8[2]+=t0.z; a8[3]+=t0.w;
        a8[4]+=t1.x; a8[5]+=t1.y; a8[6]+=t1.z; a8[7]+=t1.w;
    }
#pragma unroll
    for (int k = 0; k < 8; k++) a8[k] = fmaxf(a8[k]*sc0 + pc0, 0.f);   // bn0 + relu

    // w_rank stage: pair-packed const weights
    u64 r2p0[16], r2p1[16];
#pragma unroll
    for (int hh = 0; hh < 2; hh++) {
        u64 b0p = pk(a8[hh*4+0], a8[hh*4+0]);
        u64 b1p = pk(a8[hh*4+1], a8[hh*4+1]);
        u64 b2p = pk(a8[hh*4+2], a8[hh*4+2]);
        u64 b3p = pk(a8[hh*4+3], a8[hh*4+3]);
#pragma unroll
        for (int oo = 0; oo < 16; oo++) {
            u64 e = sbasep[oo];
            const ulonglong2* wq = reinterpret_cast<const ulonglong2*>(&c_wrp[oo*8]);
            ulonglong2 wa = wq[0], wb = wq[1];
            e = ffma2(b0p, wa.x, e);
            e = ffma2(b1p, wa.y, e);
            e = ffma2(b2p, wb.x, e);
            e = ffma2(b3p, wb.y, e);
            float e0, e1; upk(e, e0, e1);
            u64 r = pk(fmaxf(e0, 0.f), fmaxf(e1, 0.f));
            if (hh == 0) r2p0[oo] = r; else r2p1[oo] = r;
        }
    }

    // w_h1 stage: output pairs (2o2, 2o2+1) for both h rows (const weights)
    float s = 0.f, q = 0.f;
    size_t bh0 = (size_t)((c*4 + 2*hp)*16)*M + m;
#pragma unroll 2
    for (int o2 = 0; o2 < 16; o2++) {
        int oe = 2*o2, od = 2*o2 + 1;
        u64 aE0 = pk(c_bh1[oe], 0.f), aE1 = aE0;
        u64 aO0 = pk(c_bh1[od], 0.f), aO1 = aO0;
        const ulonglong2* wpe = reinterpret_cast<const ulonglong2*>(&c_wh1[oe*32]);
        const ulonglong2* wpo = reinterpret_cast<const ulonglong2*>(&c_wh1[od*32]);
#pragma unroll
        for (int i = 0; i < 8; i++) {
            ulonglong2 we = wpe[i], wo = wpo[i];
            aE0 = ffma2(r2p0[2*i], we.x, aE0); aE0 = ffma2(r2p0[2*i+1], we.y, aE0);
            aE1 = ffma2(r2p1[2*i], we.x, aE1); aE1 = ffma2(r2p1[2*i+1], we.y, aE1);
            aO0 = ffma2(r2p0[2*i], wo.x, aO0); aO0 = ffma2(r2p0[2*i+1], wo.y, aO0);
            aO1 = ffma2(r2p1[2*i], wo.x, aO1); aO1 = ffma2(r2p1[2*i+1], wo.y, aO1);
        }
        float e0l,e0h,e1l,e1h,o0l,o0h,o1l,o1h;
        upk(aE0,e0l,e0h); upk(aE1,e1l,e1h); upk(aO0,o0l,o0h); upk(aO1,o1l,o1h);
        float vE0 = e0l+e0h, vE1 = e1l+e1h, vO0 = o0l+o0h, vO1 = o1l+o1h;
        s += vE0 + vE1 + vO0 + vO1;
        q += vE0*vE0 + vE1*vE1 + vO0*vO0 + vO1*vO1;
        g_r3h[bh0 + (size_t)o2*M]        = __floats2half2_rn(vE0, vO0);   // h0
        g_r3h[bh0 + (size_t)(16+o2)*M]   = __floats2half2_rn(vE1, vO1);   // h0+1
    }
    for (int off = 16; off; off >>= 1) {
        s += __shfl_down_sync(0xffffffffu, s, off);
        q += __shfl_down_sync(0xffffffffu, q, off);
    }
    if ((t & 31) == 0) { atomicAdd(&red_s, s); atomicAdd(&red_q, q); }
    __syncthreads();
    if (t == 0) { atomicAdd(&g_bn1s[c], red_s); atomicAdd(&g_bn1q[c], red_q); }
}

// ---------------- k5: round-15 body + inline BN1 finalize (all-const weights) -
__global__ void __launch_bounds__(256, 3) k5(const float* __restrict__ bn1_g,
                                             const float* __restrict__ bn1_b) {
    __shared__ float red_s, red_q;
    int c = blockIdx.y, t = threadIdx.x;
    if (t == 0) { red_s = 0.f; red_q = 0.f; }
    __syncthreads();

    // BN1 finalize (uniform, cheap, redundant per thread)
    float n1   = (float)M * 11.0f * 32.0f;
    float mean = g_bn1s[c] / n1;
    float var  = g_bn1q[c] / n1 - mean*mean;
    float sc1  = bn1_g[c] * rsqrtf(var + BNEPS);
    float sf1  = bn1_b[c] - mean*sc1;

    int hp = t >> 7;
    int m  = blockIdx.x*128 + (t & 127);

    u64 yp0[16], yp1[16];
    size_t rb = (size_t)((c*4 + 2*hp)*16)*M + m;
#pragma unroll
    for (int i2 = 0; i2 < 16; i2++) {
        float2 f = __half22float2(g_r3h[rb + (size_t)i2*M]);
        yp0[i2] = pk(fmaxf(f.x*sc1 + sf1, 0.f), fmaxf(f.y*sc1 + sf1, 0.f));
    }
#pragma unroll
    for (int i2 = 0; i2 < 16; i2++) {
        float2 f = __half22float2(g_r3h[rb + (size_t)(16 + i2)*M]);
        yp1[i2] = pk(fmaxf(f.x*sc1 + sf1, 0.f), fmaxf(f.y*sc1 + sf1, 0.f));
    }

    float s = 0.f, q = 0.f;
    size_t wb = (size_t)(c*32)*M + m;
#pragma unroll 2
    for (int o2 = 0; o2 < 8; o2++) {
        int oe = 2*o2, od = 2*o2 + 1;
        u64 aE0 = pk(c_bh2[oe], 0.f), aE1 = aE0;
        u64 aO0 = pk(c_bh2[od], 0.f), aO1 = aO0;
        const ulonglong2* wpe = reinterpret_cast<const ulonglong2*>(&c_wh2[oe*32]);
        const ulonglong2* wpo = reinterpret_cast<const ulonglong2*>(&c_wh2[od*32]);
#pragma unroll
        for (int i = 0; i < 8; i++) {
            ulonglong2 we = wpe[i], wo = wpo[i];
            aE0 = ffma2(yp0[2*i], we.x, aE0); aE0 = ffma2(yp0[2*i+1], we.y, aE0);
            aE1 = ffma2(yp1[2*i], we.x, aE1); aE1 = ffma2(yp1[2*i+1], we.y, aE1);
            aO0 = ffma2(yp0[2*i], wo.x, aO0); aO0 = ffma2(yp0[2*i+1], wo.y, aO0);
            aO1 = ffma2(yp1[2*i], wo.x, aO1); aO1 = ffma2(yp1[2*i+1], wo.y, aO1);
        }
        float e0l,e0h,e1l,e1h,o0l,o0h,o1l,o1h;
        upk(aE0,e0l,e0h); upk(aE1,e1l,e1h); upk(aO0,o0l,o0h); upk(aO1,o1l,o1h);
        float vE0 = e0l+e0h, vE1 = e1l+e1h, vO0 = o0l+o0h, vO1 = o1l+o1h;
        s += vE0 + vE1 + vO0 + vO1;
        q += vE0*vE0 + vE1*vE1 + vO0*vO0 + vO1*vO1;
        g_r4h[wb + (size_t)((2*hp)*8   + o2)*M] = __floats2half2_rn(vE0, vO0);
        g_r4h[wb + (size_t)((2*hp+1)*8 + o2)*M] = __floats2half2_rn(vE1, vO1);
    }
    for (int off = 16; off; off >>= 1) {
        s += __shfl_down_sync(0xffffffffu, s, off);
        q += __shfl_down_sync(0xffffffffu, q, off);
    }
    if ((t & 31) == 0) { atomicAdd(&red_s, s); atomicAdd(&red_q, q); }
    __syncthreads();
    if (t == 0) { atomicAdd(&g_bn2s[c], red_s); atomicAdd(&g_bn2q[c], red_q); }
}

// ---------------- k6: const w_h2 path + BN2 finalize + const-row output -------
// 16 blocks x 288 threads. Block b: channels [4b, 4b+4), feature slice 64.
__global__ void __launch_bounds__(288) k6(const float* __restrict__ bn1_g,
                                          const float* __restrict__ bn1_b,
                                          const float* __restrict__ bn2_g,
                                          const float* __restrict__ bn2_b,
                                          const float* __restrict__ w_h2,
                                          const float* __restrict__ b_h2,
                                          const float* __restrict__ w_out) {
    __shared__ float swh2T[32*17];
    __shared__ float rc3bn[4][32];
    __shared__ float rc4s[4][16];
    __shared__ float rc5[64];
    __shared__ float s_sc2[4], s_sh2[4];
    int t = threadIdx.x, b = blockIdx.x;
    int warp = t >> 5, lane = t & 31;
    for (int idx = t; idx < 512; idx += 288) {
        int o = idx >> 5, i = idx & 31;
        swh2T[i*17 + o] = w_h2[idx];
    }
    if (warp < 4) {                                   // BN1 finalize + rc3bn
        int c = b*4 + warp;
        float n1   = (float)M * 11.0f * 32.0f;
        float mean = g_bn1s[c] / n1;
        float var  = g_bn1q[c] / n1 - mean*mean;
        float sc1  = bn1_g[c] * rsqrtf(var + BNEPS);
        float sf1  = bn1_b[c] - mean*sc1;
        rc3bn[warp][lane] = fmaxf(g_rc3[c*32 + lane]*sc1 + sf1, 0.f);
    }
    __syncthreads();
    if (warp < 4) {                                   // const w_h2 matvec + BN2 finalize
        int c = b*4 + warp;
        float acc = 0.f;
        bool act = lane < 16;
        if (act) {
            acc = b_h2[lane];
#pragma unroll
            for (int i = 0; i < 32; i++) acc += rc3bn[warp][i] * swh2T[i*17 + lane];
            rc4s[warp][lane] = acc;
        }
        float s = act ? acc : 0.f, q = act ? acc*acc : 0.f;
        for (int off = 16; off; off >>= 1) {
            s += __shfl_down_sync(0xffffffffu, s, off);
            q += __shfl_down_sync(0xffffffffu, q, off);
        }
        if (lane == 0) {
            float n2   = (float)M * 11.0f * 16.0f;
            float tots = g_bn2s[c] + (float)(M*7)*s;
            float totq = g_bn2q[c] + (float)(M*7)*q;
            float mean = tots / n2;
            float var  = totq / n2 - mean*mean;
            float sc2  = bn2_g[c] * rsqrtf(var + BNEPS);
            float sh2  = bn2_b[c] - mean*sc2;
            g_scale2[c] = sc2;  s_sc2[warp] = sc2;
            g_shift2[c] = sh2;  s_sh2[warp] = sh2;
        }
    }
    __syncthreads();
    if (t < 64) {
        int lc = t >> 4;
        rc5[t] = fmaxf(rc4s[lc][t & 15]*s_sc2[lc] + s_sh2[lc], 0.f);
    }
    __syncthreads();
    int j = warp;
    if (j < 9) {
        float acc = 0.f;
#pragma unroll
        for (int rep = 0; rep < 2; rep++) {
            int p = rep*32 + lane;
            int gp = b*64 + p;
            int c = gp >> 4, o = gp & 15;
            float ws = 0.f;
#pragma unroll
            for (int h = 4; h < 11; h++) ws += w_out[j*11264 + c*176 + h*16 + o];
            acc += rc5[p]*ws;
        }
        for (int off = 16; off; off >>= 1) acc += __shfl_down_sync(0xffffffffu, acc, off);
        if (!lane) atomicAdd(&g_outconst[j], acc);
    }
}

// ---------------- k6b: seed output with constant part -------------------------
__global__ void k6b(float* __restrict__ out) {
    int idx = blockIdx.x*256 + threadIdx.x;
    if (idx < M*9) out[idx] = g_outconst[idx % 9];
}

// ---------------- k7: varying-feature GEMM (bn2+relu fused, fp16 in) ----------
__global__ void __launch_bounds__(256) k7(const float* __restrict__ w_out,
                                          float* __restrict__ out) {
    __shared__ u64 swe[9*32], swo[9*32];
    int t = threadIdx.x;
    int warp = t >> 5, lane = t & 31;
    int mbase = blockIdx.x*1024 + warp*128 + lane*4;
    int c0 = blockIdx.y*2;
    u64 accA[9], accB[9];
#pragma unroll
    for (int j = 0; j < 9; j++) { accA[j] = 0; accB[j] = 0; }
    for (int cc = 0; cc < 2; cc++) {
        int c = c0 + cc;
        __syncthreads();
        for (int idx = t; idx < 576; idx += 256) {
            int j = idx / 64, r = idx % 64, qq2 = r >> 1, eo = r & 1;
            int h = qq2 >> 3, o2 = qq2 & 7;
            float w = w_out[j*11264 + c*176 + h*16 + 2*o2 + eo];
            (eo ? swo : swe)[j*32 + qq2] = pk(w, w);
        }
        __syncthreads();
        float sc = g_scale2[c], sf = g_shift2[c];
        for (int qq2 = 0; qq2 < 32; qq2++) {
            const __half2* row = &g_r4h[(size_t)(c*32 + qq2)*M];
            uint2 ua = *reinterpret_cast<const uint2*>(row + mbase);
            uint2 ub = *reinterpret_cast<const uint2*>(row + mbase + 2);
            float2 f0 = __half22float2(*reinterpret_cast<__half2*>(&ua.x));
            float2 f1 = __half22float2(*reinterpret_cast<__half2*>(&ua.y));
            float2 f2 = __half22float2(*reinterpret_cast<__half2*>(&ub.x));
            float2 f3 = __half22float2(*reinterpret_cast<__half2*>(&ub.y));
            u64 yeA = pk(fmaxf(f0.x*sc+sf, 0.f), fmaxf(f1.x*sc+sf, 0.f));
            u64 yoA = pk(fmaxf(f0.y*sc+sf, 0.f), fmaxf(f1.y*sc+sf, 0.f));
            u64 yeB = pk(fmaxf(f2.x*sc+sf, 0.f), fmaxf(f3.x*sc+sf, 0.f));
            u64 yoB = pk(fmaxf(f2.y*sc+sf, 0.f), fmaxf(f3.y*sc+sf, 0.f));
#pragma unroll
            for (int j = 0; j < 9; j++) {
                u64 we = swe[j*32 + qq2], wo = swo[j*32 + qq2];
                accA[j] = ffma2(yeA, we, accA[j]);
                accA[j] = ffma2(yoA, wo, accA[j]);
                accB[j] = ffma2(yeB, we, accB[j]);
                accB[j] = ffma2(yoB, wo, accB[j]);
            }
        }
    }
#pragma unroll
    for (int j = 0; j < 9; j++) {
        float a0, a1, b0, b1;
        upk(accA[j], a0, a1);
        upk(accB[j], b0, b1);
        atomicAdd(&out[(size_t)mbase*9 + j],     a0);
        atomicAdd(&out[(size_t)(mbase+1)*9 + j], a1);
        atomicAdd(&out[(size_t)(mbase+2)*9 + j], b0);
        atomicAdd(&out[(size_t)(mbase+3)*9 + j], b1);
    }
}

// ---------------- launch ------------------------------------------------------
extern "C" void kernel_launch(void* const* d_in, const int* in_sizes, int n_in,
                              void* d_out, int out_size) {
    const int*   x      = (const int*)  d_in[0];
    const float* conv_w = (const float*)d_in[1];
    const float* conv_b = (const float*)d_in[2];
    const float* bn0_g  = (const float*)d_in[3];
    const float* bn0_b  = (const float*)d_in[4];
    const float* w_rank = (const float*)d_in[5];
    const float* b_rank = (const float*)d_in[6];
    const float* w_h1   = (const float*)d_in[7];
    const float* b_h1   = (const float*)d_in[8];
    const float* bn1_g  = (const float*)d_in[9];
    const float* bn1_b  = (const float*)d_in[10];
    const float* w_h2   = (const float*)d_in[11];
    const float* b_h2   = (const float*)d_in[12];
    const float* bn2_g  = (const float*)d_in[13];
    const float* bn2_b  = (const float*)d_in[14];
    const float* w_out  = (const float*)d_in[15];
    const float* b_out  = (const float*)d_in[16];
    float* out = (float*)d_out;

    ktable<<<87, 1024>>>(conv_w, x, w_rank, b_rank, w_h1, b_h1, w_h2, b_h2);
    void* stage_ptr = nullptr;
    cudaGetSymbolAddress(&stage_ptr, g_stage);
    cudaMemcpyToSymbolAsync(c_all, stage_ptr, 2064*sizeof(float), 0,
                            cudaMemcpyDeviceToDevice, 0);

    kbn0k2<<<64, 256>>>(conv_b, bn0_g, bn0_b, w_rank, b_rank, w_h1, b_h1, b_out);
    k3<<<dim3(32, 64), 256>>>(x, conv_b);
    k5<<<dim3(32, 64), 256>>>(bn1_g, bn1_b);
    k6<<<16, 288>>>(bn1_g, bn1_b, bn2_g, bn2_b, w_h2, b_h2, w_out);
    k6b<<<144, 256>>>(out);
    k7<<<dim3(4, 32), 256>>>(w_out, out);
}